// round 16
// baseline (speedup 1.0000x reference)
#include <cuda_runtime.h>
#include <cstdint>

#define BATCH 4
#define C3 256
#define HH 48
#define WW 48
#define L 2304      // HH*WW positions
#define LP1 2305    // L+1, diagonal shift stride
#define LCHUNK 64
// guard margin >= 49*LP1 floats each side, rounded UP to multiple of 4 so that
// Gram rows stay 16B-aligned (L % 8 == 0). 49*LP1 = 112945 -> 112948.
#define GUARD (((49 * LP1) + 3) & ~3)

// ---------------- device scratch (no allocs allowed) ----------------
__device__ float g_Gbuf[(size_t)BATCH * L * L + 2 * (size_t)GUARD];  // guarded Gram
__device__ float g_Prs[BATCH * L];
__device__ float g_Plr[BATCH * L];
__device__ float g_invA[BATCH * L];
__device__ float g_invB[BATCH * L];
__device__ unsigned long long g_best[BATCH * L];
__device__ int g_arg[BATCH * L];

// monotonic float<->uint key (total order matching float compare)
__device__ __forceinline__ unsigned fkey(float f) {
    unsigned u = __float_as_uint(f);
    return (u & 0x80000000u) ? ~u : (u | 0x80000000u);
}
__device__ __forceinline__ float fkeyinv(unsigned k) {
    unsigned u = (k & 0x80000000u) ? (k & 0x7FFFFFFFu) : ~k;
    return __uint_as_float(u);
}

// packed f32x2 FMA (Blackwell FFMA2 — only reachable via PTX)
__device__ __forceinline__ unsigned long long fma2(unsigned long long a,
                                                   unsigned long long b,
                                                   unsigned long long c) {
    unsigned long long d;
    asm("fma.rn.f32x2 %0, %1, %2, %3;" : "=l"(d) : "l"(a), "l"(b), "l"(c));
    return d;
}
__device__ __forceinline__ unsigned long long dup2(float x) {
    unsigned long long r;
    asm("mov.b64 %0, {%1, %1};" : "=l"(r) : "f"(x));
    return r;
}

// cp.async helpers (base PTX, sm_80+)
__device__ __forceinline__ uint32_t smem_u32(const void* p) {
    uint32_t a;
    asm("{ .reg .u64 t; cvta.to.shared.u64 t, %1; cvt.u32.u64 %0, t; }" : "=r"(a) : "l"(p));
    return a;
}
__device__ __forceinline__ void cp_async16(uint32_t dst, const void* src) {
    asm volatile("cp.async.cg.shared.global [%0], [%1], 16;" :: "r"(dst), "l"(src)
                 : "memory");
}
__device__ __forceinline__ void cp_commit() {
    asm volatile("cp.async.commit_group;" ::: "memory");
}
template <int N>
__device__ __forceinline__ void cp_wait() {
    asm volatile("cp.async.wait_group %0;" :: "n"(N) : "memory");
}

// ---------------- 0. init partial-sum buffers ----------------
__global__ void k_init() {
    int i = blockIdx.x * blockDim.x + threadIdx.x;
    if (i < BATCH * L) { g_Prs[i] = 0.f; g_Plr[i] = 0.f; }
}

// ---------------- 1. per-pixel channel squared sums (channel-split) ----------------
__global__ void k_sqsum(const float* __restrict__ lrsr, const float* __restrict__ refsr) {
    int b = blockIdx.z;
    int p = blockIdx.x * 256 + threadIdx.x;
    int cbase = blockIdx.y * 32;
    size_t base = (size_t)b * C3 * L + (size_t)cbase * L + p;
    float srs = 0.f, slr = 0.f;
    #pragma unroll 8
    for (int c = 0; c < 32; c++) {
        float v = refsr[base + (size_t)c * L];
        srs = fmaf(v, v, srs);
        v = lrsr[base + (size_t)c * L];
        slr = fmaf(v, v, slr);
    }
    atomicAdd(&g_Prs[b * L + p], srs);
    atomicAdd(&g_Plr[b * L + p], slr);
}

// ---------------- 2. 3x3 window norms + best-init ----------------
__global__ void k_norms() {
    int i = blockIdx.x * blockDim.x + threadIdx.x;
    if (i >= BATCH * L) return;
    int b = i / L, p = i % L, y = p / WW, x = p % WW;
    float wr = 0.f, wl = 0.f;
    #pragma unroll
    for (int dy = -1; dy <= 1; dy++) {
        int yy = y + dy;
        if ((unsigned)yy >= HH) continue;
        #pragma unroll
        for (int dx = -1; dx <= 1; dx++) {
            int xx = x + dx;
            if ((unsigned)xx >= WW) continue;
            wr += g_Prs[b * L + yy * WW + xx];
            wl += g_Plr[b * L + yy * WW + xx];
        }
    }
    g_invA[i] = 1.f / fmaxf(sqrtf(wr), 1e-12f);
    g_invB[i] = 1.f / fmaxf(sqrtf(wl), 1e-12f);
    g_best[i] = 0ull;  // key 0 < any real float key
}

// ---------------- 3. Gram GEMM: G[l][m] = sum_c refsr[c][l] * lrsr[c][m] ----------------
// 128x128 tile, 8x8 micro-tile FFMA2, K-chunk 16, 3-stage cp.async pipeline.
#define KC 16        // K rows per chunk
#define NCH (C3 / KC)
__global__ void __launch_bounds__(256, 2) k_gemmG(const float* __restrict__ refsr,
                                                  const float* __restrict__ lrsr) {
    int b = blockIdx.z;
    int lbase = blockIdx.y * 128;
    int mbase = blockIdx.x * 128;
    const float* A = refsr + (size_t)b * C3 * L;   // [k][l]
    const float* Bm = lrsr + (size_t)b * C3 * L;   // [k][m]

    __shared__ float As[3][KC][128];
    __shared__ float Bs[3][KC][128];

    int t = threadIdx.x;
    int tx = t & 15, ty = t >> 4;

    unsigned long long acc[8][4];
    #pragma unroll
    for (int i = 0; i < 8; i++)
        #pragma unroll
        for (int j = 0; j < 4; j++) acc[i][j] = 0ull;  // (0.f, 0.f)

    int kr2 = t >> 4;
    int co8 = (t & 15) << 3;
    const float* ag = A + (size_t)kr2 * L + lbase + co8;
    const float* bg = Bm + (size_t)kr2 * L + mbase + co8;

    uint32_t sA[3], sB[3];
    #pragma unroll
    for (int s = 0; s < 3; s++) {
        sA[s] = smem_u32(&As[s][kr2][co8]);
        sB[s] = smem_u32(&Bs[s][kr2][co8]);
    }

    #pragma unroll
    for (int ch = 0; ch < 2; ch++) {
        size_t go = (size_t)(ch * KC) * L;
        cp_async16(sA[ch], ag + go);
        cp_async16(sA[ch] + 16, ag + go + 4);
        cp_async16(sB[ch], bg + go);
        cp_async16(sB[ch] + 16, bg + go + 4);
        cp_commit();
    }

    #pragma unroll 1
    for (int ch = 0; ch < NCH; ch++) {
        if (ch + 1 < NCH) cp_wait<1>(); else cp_wait<0>();
        __syncthreads();
        if (ch + 2 < NCH) {
            int st = (ch + 2) % 3;
            size_t go = (size_t)((ch + 2) * KC) * L;
            cp_async16(sA[st], ag + go);
            cp_async16(sA[st] + 16, ag + go + 4);
            cp_async16(sB[st], bg + go);
            cp_async16(sB[st] + 16, bg + go + 4);
            cp_commit();
        }
        int buf = ch % 3;
        #pragma unroll
        for (int k = 0; k < KC; k++) {
            const ulonglong2* brow = (const ulonglong2*)&Bs[buf][k][tx * 8];
            ulonglong2 b01 = brow[0];
            ulonglong2 b23 = brow[1];
            float a[8];
            *(float4*)&a[0] = *(const float4*)&As[buf][k][ty * 8];
            *(float4*)&a[4] = *(const float4*)&As[buf][k][ty * 8 + 4];
            #pragma unroll
            for (int i = 0; i < 8; i++) {
                unsigned long long ap = dup2(a[i]);
                acc[i][0] = fma2(ap, b01.x, acc[i][0]);
                acc[i][1] = fma2(ap, b01.y, acc[i][1]);
                acc[i][2] = fma2(ap, b23.x, acc[i][2]);
                acc[i][3] = fma2(ap, b23.y, acc[i][3]);
            }
        }
    }

    float* gout = g_Gbuf + GUARD + (size_t)b * L * L;
    #pragma unroll
    for (int i = 0; i < 8; i++) {
        size_t row = (size_t)(lbase + ty * 8 + i) * L + mbase + tx * 8;
        *(ulonglong2*)&gout[row + 0] = make_ulonglong2(acc[i][0], acc[i][1]);
        *(ulonglong2*)&gout[row + 4] = make_ulonglong2(acc[i][2], acc[i][3]);
    }
}

// ---------------- 4. diagonal 3x3 box filter of G + scaling + column argmax ----------------
// Unpredicated loads (guards stay zero), 4-row unroll for deep MLP.
__global__ void __launch_bounds__(256) k_boxargmax() {
    int b = blockIdx.z;
    int m = blockIdx.x * 256 + threadIdx.x;
    int l0 = blockIdx.y * LCHUNK;
    int my = m / WW, mx = m % WW;

    __shared__ float sInvA[LCHUNK];
    __shared__ unsigned sLmask[LCHUNK];
    int t = threadIdx.x;
    if (t < LCHUNK) {
        int l = l0 + t, ly = l / WW, lx = l % WW;
        unsigned msk = 0;
        int o = 0;
        #pragma unroll
        for (int dy = -1; dy <= 1; dy++)
            #pragma unroll
            for (int dx = -1; dx <= 1; dx++, o++)
                if ((unsigned)(ly + dy) < HH && (unsigned)(lx + dx) < WW)
                    msk |= 1u << o;
        sLmask[t] = msk;
        sInvA[t] = g_invA[b * L + l];
    }
    __syncthreads();

    unsigned mmask = 0;
    {
        int o = 0;
        #pragma unroll
        for (int dy = -1; dy <= 1; dy++)
            #pragma unroll
            for (int dx = -1; dx <= 1; dx++, o++)
                if ((unsigned)(my + dy) < HH && (unsigned)(mx + dx) < WW)
                    mmask |= 1u << o;
    }

    const float invBm = g_invB[b * L + m];
    const float* gbase = g_Gbuf + GUARD + (size_t)b * L * L + (size_t)l0 * L + m;
    const int doff[9] = {-49 * LP1, -48 * LP1, -47 * LP1, -LP1, 0,
                         LP1, 47 * LP1, 48 * LP1, 49 * LP1};

    float best = -1e30f;
    int barg = l0;
    for (int i = 0; i < LCHUNK; i += 4) {
        float v[4][9];
        #pragma unroll
        for (int r = 0; r < 4; r++) {
            const float* pr = gbase + (size_t)(i + r) * L;
            #pragma unroll
            for (int o = 0; o < 9; o++)
                v[r][o] = __ldg(pr + doff[o]);   // unconditional: guards are zero
        }
        #pragma unroll
        for (int r = 0; r < 4; r++) {
            unsigned mk = sLmask[i + r] & mmask;
            float s = 0.f;
            #pragma unroll
            for (int o = 0; o < 9; o++)
                s += ((mk >> o) & 1) ? v[r][o] : 0.f;
            float wv = s * sInvA[i + r] * invBm;
            if (wv > best) { best = wv; barg = l0 + i + r; }
        }
    }

    unsigned long long pk = ((unsigned long long)fkey(best) << 32) |
                            (unsigned long long)(0xFFFFFFFFu - (unsigned)barg);
    atomicMax(&g_best[b * L + m], pk);
}

// ---------------- 5. decode best -> S output + arg indices ----------------
__global__ void k_decode(float* __restrict__ outS) {
    int i = blockIdx.x * blockDim.x + threadIdx.x;
    if (i >= BATCH * L) return;
    unsigned long long p = g_best[i];
    outS[i] = fkeyinv((unsigned)(p >> 32));
    g_arg[i] = (int)(0xFFFFFFFFu - (unsigned)(p & 0xFFFFFFFFu));
}

// ---------------- 6a. gather s=1 (T3): scalar fixed-9 masked loads ----------------
__global__ void k_gather1(const float* __restrict__ ref, float* __restrict__ out) {
    const int C = C3, Hs = 48;
    int b = blockIdx.z;
    int cbase = blockIdx.y * 8;
    int p = blockIdx.x * blockDim.x + threadIdx.x;
    int y = p / Hs, x = p % Hs;
    const int* argb = g_arg + b * L;

    int off[9];
    float w[9];
    {
        int o = 0;
        #pragma unroll
        for (int dy = 0; dy < 3; dy++) {
            int oh = y + 1 - dy;
            #pragma unroll
            for (int dx = 0; dx < 3; dx++, o++) {
                int ow = x + 1 - dx;
                bool v = (unsigned)oh < HH && (unsigned)ow < WW;
                int j = v ? __ldg(argb + oh * WW + ow) : 0;
                int sy = (j / WW) + dy - 1;
                int sx = (j % WW) + dx - 1;
                v = v && (unsigned)sy < (unsigned)Hs && (unsigned)sx < (unsigned)Hs;
                off[o] = v ? (sy * Hs + sx) : 0;
                w[o] = v ? 1.f : 0.f;
            }
        }
    }

    size_t plane = (size_t)Hs * Hs;
    const float* refc = ref + ((size_t)b * C + cbase) * plane;
    float* outc = out + ((size_t)b * C + cbase) * plane + p;
    #pragma unroll
    for (int cc = 0; cc < 8; cc++) {
        const float* rp = refc + (size_t)cc * plane;
        float sum = 0.f;
        #pragma unroll
        for (int o = 0; o < 9; o++)
            sum = fmaf(w[o], __ldg(rp + off[o]), sum);
        outc[(size_t)cc * plane] = sum * (1.f / 9.f);
    }
}

// ---------------- 6b. gather s=2 (T2): float2-vectorized over the s-group ----------------
// The 2 pixels of an s-group share j; source cols are consecutive & 2-aligned.
__global__ void k_gather2(const float* __restrict__ ref, float* __restrict__ out) {
    const int C = 128, Hs = 96, s = 2;
    int b = blockIdx.z;
    int cbase = blockIdx.y * 8;
    int g = blockIdx.x * blockDim.x + threadIdx.x;  // y * 48 + qx
    int y = g / WW, qx = g % WW;
    int qy = y >> 1, ry = y & 1;
    const int* argb = g_arg + b * L;

    int off[9];
    float w[9];
    {
        int o = 0;
        #pragma unroll
        for (int dy = 0; dy < 3; dy++) {
            int oh = qy + 1 - dy;
            int ki = ry + s * dy;
            #pragma unroll
            for (int dx = 0; dx < 3; dx++, o++) {
                int ow = qx + 1 - dx;
                bool v = (unsigned)oh < HH && (unsigned)ow < WW;
                int j = v ? __ldg(argb + oh * WW + ow) : 0;
                int sy = s * (j / WW) + ki - s;
                int sxb = s * ((j % WW) + dx - 1);
                v = v && (unsigned)sy < (unsigned)Hs && (unsigned)sxb < (unsigned)Hs;
                off[o] = v ? (sy * Hs + sxb) : 0;
                w[o] = v ? 1.f : 0.f;
            }
        }
    }

    size_t plane = (size_t)Hs * Hs;
    const float* refc = ref + ((size_t)b * C + cbase) * plane;
    float* outc = out + ((size_t)b * C + cbase) * plane + y * Hs + qx * s;
    #pragma unroll
    for (int cc = 0; cc < 8; cc++) {
        const float* rp = refc + (size_t)cc * plane;
        float s0 = 0.f, s1 = 0.f;
        #pragma unroll
        for (int o = 0; o < 9; o++) {
            float2 v2 = *(const float2*)(rp + off[o]);
            s0 = fmaf(w[o], v2.x, s0);
            s1 = fmaf(w[o], v2.y, s1);
        }
        *(float2*)(outc + (size_t)cc * plane) =
            make_float2(s0 * (1.f / 9.f), s1 * (1.f / 9.f));
    }
}

// ---------------- 6c. gather s=4 (T1): float4-vectorized over the s-group ----------------
__global__ void k_gather4(const float* __restrict__ ref, float* __restrict__ out) {
    const int C = 64, Hs = 192, s = 4;
    int b = blockIdx.z;
    int cbase = blockIdx.y * 8;
    int g = blockIdx.x * blockDim.x + threadIdx.x;  // y * 48 + qx
    int y = g / WW, qx = g % WW;
    int qy = y >> 2, ry = y & 3;
    const int* argb = g_arg + b * L;

    int off[9];
    float w[9];
    {
        int o = 0;
        #pragma unroll
        for (int dy = 0; dy < 3; dy++) {
            int oh = qy + 1 - dy;
            int ki = ry + s * dy;
            #pragma unroll
            for (int dx = 0; dx < 3; dx++, o++) {
                int ow = qx + 1 - dx;
                bool v = (unsigned)oh < HH && (unsigned)ow < WW;
                int j = v ? __ldg(argb + oh * WW + ow) : 0;
                int sy = s * (j / WW) + ki - s;
                int sxb = s * ((j % WW) + dx - 1);
                v = v && (unsigned)sy < (unsigned)Hs && (unsigned)sxb < (unsigned)Hs;
                off[o] = v ? (sy * Hs + sxb) : 0;
                w[o] = v ? 1.f : 0.f;
            }
        }
    }

    size_t plane = (size_t)Hs * Hs;
    const float* refc = ref + ((size_t)b * C + cbase) * plane;
    float* outc = out + ((size_t)b * C + cbase) * plane + y * Hs + qx * s;
    #pragma unroll
    for (int cc = 0; cc < 8; cc++) {
        const float* rp = refc + (size_t)cc * plane;
        float s0 = 0.f, s1 = 0.f, s2 = 0.f, s3 = 0.f;
        #pragma unroll
        for (int o = 0; o < 9; o++) {
            float4 v4 = *(const float4*)(rp + off[o]);
            s0 = fmaf(w[o], v4.x, s0);
            s1 = fmaf(w[o], v4.y, s1);
            s2 = fmaf(w[o], v4.z, s2);
            s3 = fmaf(w[o], v4.w, s3);
        }
        *(float4*)(outc + (size_t)cc * plane) =
            make_float4(s0 * (1.f / 9.f), s1 * (1.f / 9.f),
                        s2 * (1.f / 9.f), s3 * (1.f / 9.f));
    }
}

// ---------------- launch ----------------
extern "C" void kernel_launch(void* const* d_in, const int* in_sizes, int n_in,
                              void* d_out, int out_size) {
    const float* lrsr = (const float*)d_in[0];
    const float* refsr = (const float*)d_in[1];
    const float* ref1 = (const float*)d_in[2];
    const float* ref2 = (const float*)d_in[3];
    const float* ref3 = (const float*)d_in[4];
    float* out = (float*)d_out;

    float* outS = out;                            // (4,1,48,48)
    float* outT3 = outS + BATCH * L;              // (4,256,48,48)
    float* outT2 = outT3 + BATCH * C3 * HH * WW;  // (4,128,96,96)
    float* outT1 = outT2 + BATCH * 128 * 96 * 96; // (4,64,192,192)

    k_init<<<(BATCH * L + 255) / 256, 256>>>();
    k_sqsum<<<dim3(9, 8, BATCH), 256>>>(lrsr, refsr);
    k_norms<<<(BATCH * L + 255) / 256, 256>>>();
    k_gemmG<<<dim3(18, 18, BATCH), 256>>>(refsr, lrsr);
    k_boxargmax<<<dim3(9, 36, BATCH), 256>>>();
    k_decode<<<(BATCH * L + 255) / 256, 256>>>(outS);
    k_gather1<<<dim3(2304 / 256, C3 / 8, BATCH), 256>>>(ref3, outT3);
    k_gather2<<<dim3(96 * 48 / 256, 128 / 8, BATCH), 256>>>(ref2, outT2);
    k_gather4<<<dim3(192 * 48 / 256, 64 / 8, BATCH), 256>>>(ref1, outT1);
}

// round 17
// speedup vs baseline: 1.1458x; 1.1458x over previous
#include <cuda_runtime.h>
#include <cstdint>

#define BATCH 4
#define C3 256
#define HH 48
#define WW 48
#define L 2304      // HH*WW positions
#define LP1 2305    // L+1, diagonal shift stride
#define LCHUNK 64
// guard margin >= 49*LP1 floats each side, rounded UP to multiple of 4 so that
// Gram rows stay 16B-aligned (L % 8 == 0). 49*LP1 = 112945 -> 112948.
#define GUARD (((49 * LP1) + 3) & ~3)

// ---------------- device scratch (no allocs allowed) ----------------
__device__ float g_Gbuf[(size_t)BATCH * L * L + 2 * (size_t)GUARD];  // guarded Gram
__device__ float g_Prs[BATCH * L];
__device__ float g_Plr[BATCH * L];
__device__ float g_invA[BATCH * L];
__device__ float g_invB[BATCH * L];
__device__ unsigned long long g_best[BATCH * L];
__device__ int g_arg[BATCH * L];

// monotonic float<->uint key (total order matching float compare)
__device__ __forceinline__ unsigned fkey(float f) {
    unsigned u = __float_as_uint(f);
    return (u & 0x80000000u) ? ~u : (u | 0x80000000u);
}
__device__ __forceinline__ float fkeyinv(unsigned k) {
    unsigned u = (k & 0x80000000u) ? (k & 0x7FFFFFFFu) : ~k;
    return __uint_as_float(u);
}

// packed f32x2 FMA (Blackwell FFMA2 — only reachable via PTX)
__device__ __forceinline__ unsigned long long fma2(unsigned long long a,
                                                   unsigned long long b,
                                                   unsigned long long c) {
    unsigned long long d;
    asm("fma.rn.f32x2 %0, %1, %2, %3;" : "=l"(d) : "l"(a), "l"(b), "l"(c));
    return d;
}
__device__ __forceinline__ unsigned long long dup2(float x) {
    unsigned long long r;
    asm("mov.b64 %0, {%1, %1};" : "=l"(r) : "f"(x));
    return r;
}

// cp.async helpers (base PTX, sm_80+)
__device__ __forceinline__ uint32_t smem_u32(const void* p) {
    uint32_t a;
    asm("{ .reg .u64 t; cvta.to.shared.u64 t, %1; cvt.u32.u64 %0, t; }" : "=r"(a) : "l"(p));
    return a;
}
__device__ __forceinline__ void cp_async16(uint32_t dst, const void* src) {
    asm volatile("cp.async.cg.shared.global [%0], [%1], 16;" :: "r"(dst), "l"(src)
                 : "memory");
}
__device__ __forceinline__ void cp_commit() {
    asm volatile("cp.async.commit_group;" ::: "memory");
}
template <int N>
__device__ __forceinline__ void cp_wait() {
    asm volatile("cp.async.wait_group %0;" :: "n"(N) : "memory");
}

// ---------------- 0. init partial-sum buffers ----------------
__global__ void k_init() {
    int i = blockIdx.x * blockDim.x + threadIdx.x;
    if (i < BATCH * L) { g_Prs[i] = 0.f; g_Plr[i] = 0.f; }
}

// ---------------- 1. per-pixel channel squared sums (channel-split) ----------------
__global__ void k_sqsum(const float* __restrict__ lrsr, const float* __restrict__ refsr) {
    int b = blockIdx.z;
    int p = blockIdx.x * 256 + threadIdx.x;
    int cbase = blockIdx.y * 32;
    size_t base = (size_t)b * C3 * L + (size_t)cbase * L + p;
    float srs = 0.f, slr = 0.f;
    #pragma unroll 8
    for (int c = 0; c < 32; c++) {
        float v = refsr[base + (size_t)c * L];
        srs = fmaf(v, v, srs);
        v = lrsr[base + (size_t)c * L];
        slr = fmaf(v, v, slr);
    }
    atomicAdd(&g_Prs[b * L + p], srs);
    atomicAdd(&g_Plr[b * L + p], slr);
}

// ---------------- 2. 3x3 window norms + best-init ----------------
__global__ void k_norms() {
    int i = blockIdx.x * blockDim.x + threadIdx.x;
    if (i >= BATCH * L) return;
    int b = i / L, p = i % L, y = p / WW, x = p % WW;
    float wr = 0.f, wl = 0.f;
    #pragma unroll
    for (int dy = -1; dy <= 1; dy++) {
        int yy = y + dy;
        if ((unsigned)yy >= HH) continue;
        #pragma unroll
        for (int dx = -1; dx <= 1; dx++) {
            int xx = x + dx;
            if ((unsigned)xx >= WW) continue;
            wr += g_Prs[b * L + yy * WW + xx];
            wl += g_Plr[b * L + yy * WW + xx];
        }
    }
    g_invA[i] = 1.f / fmaxf(sqrtf(wr), 1e-12f);
    g_invB[i] = 1.f / fmaxf(sqrtf(wl), 1e-12f);
    g_best[i] = 0ull;  // key 0 < any real float key
}

// ---------------- 3. Gram GEMM: G[l][m] = sum_c refsr[c][l] * lrsr[c][m] ----------------
// 128x128 tile, 8x8 micro-tile FFMA2, K-chunk 32 (8 barriers/CTA), 3-stage
// cp.async pipeline in DYNAMIC smem (98.3KB/CTA, 2 CTAs/SM).
#define KC 32        // K rows per chunk
#define NCH (C3 / KC)  // 8
#define GEMM_SMEM (3 * KC * 128 * 4 * 2)   // As + Bs, 3 stages
__global__ void __launch_bounds__(256, 2) k_gemmG(const float* __restrict__ refsr,
                                                  const float* __restrict__ lrsr) {
    extern __shared__ float smem[];
    float* As = smem;                    // [3][KC][128]
    float* Bs = smem + 3 * KC * 128;     // [3][KC][128]

    int b = blockIdx.z;
    int lbase = blockIdx.y * 128;
    int mbase = blockIdx.x * 128;
    const float* A = refsr + (size_t)b * C3 * L;   // [k][l]
    const float* Bm = lrsr + (size_t)b * C3 * L;   // [k][m]

    int t = threadIdx.x;
    int tx = t & 15, ty = t >> 4;

    unsigned long long acc[8][4];
    #pragma unroll
    for (int i = 0; i < 8; i++)
        #pragma unroll
        for (int j = 0; j < 4; j++) acc[i][j] = 0ull;  // (0.f, 0.f)

    // load mapping: thread t covers k-rows (t>>4) and (t>>4)+16, cols (t&15)*8..+7
    int kr2 = t >> 4;
    int co8 = (t & 15) << 3;
    const float* ag0 = A + (size_t)kr2 * L + lbase + co8;
    const float* bg0 = Bm + (size_t)kr2 * L + mbase + co8;

    uint32_t sA[3], sB[3];
    #pragma unroll
    for (int s = 0; s < 3; s++) {
        sA[s] = smem_u32(&As[(s * KC + kr2) * 128 + co8]);
        sB[s] = smem_u32(&Bs[(s * KC + kr2) * 128 + co8]);
    }
    const uint32_t ROW16 = 16u * 128u * 4u;  // +16 k-rows in bytes
    const size_t G16 = (size_t)16 * L;       // +16 k-rows in gmem

    // prologue: issue chunks 0 and 1 into stages 0 and 1
    #pragma unroll
    for (int ch = 0; ch < 2; ch++) {
        size_t go = (size_t)(ch * KC) * L;
        cp_async16(sA[ch], ag0 + go);
        cp_async16(sA[ch] + 16, ag0 + go + 4);
        cp_async16(sA[ch] + ROW16, ag0 + go + G16);
        cp_async16(sA[ch] + ROW16 + 16, ag0 + go + G16 + 4);
        cp_async16(sB[ch], bg0 + go);
        cp_async16(sB[ch] + 16, bg0 + go + 4);
        cp_async16(sB[ch] + ROW16, bg0 + go + G16);
        cp_async16(sB[ch] + ROW16 + 16, bg0 + go + G16 + 4);
        cp_commit();
    }

    #pragma unroll 1
    for (int ch = 0; ch < NCH; ch++) {
        if (ch + 1 < NCH) cp_wait<1>(); else cp_wait<0>();
        __syncthreads();
        if (ch + 2 < NCH) {
            int st = (ch + 2) % 3;
            size_t go = (size_t)((ch + 2) * KC) * L;
            cp_async16(sA[st], ag0 + go);
            cp_async16(sA[st] + 16, ag0 + go + 4);
            cp_async16(sA[st] + ROW16, ag0 + go + G16);
            cp_async16(sA[st] + ROW16 + 16, ag0 + go + G16 + 4);
            cp_async16(sB[st], bg0 + go);
            cp_async16(sB[st] + 16, bg0 + go + 4);
            cp_async16(sB[st] + ROW16, bg0 + go + G16);
            cp_async16(sB[st] + ROW16 + 16, bg0 + go + G16 + 4);
            cp_commit();
        }
        int buf = ch % 3;
        const float* Ab = &As[(buf * KC) * 128];
        const float* Bb = &Bs[(buf * KC) * 128];
        #pragma unroll
        for (int k = 0; k < KC; k++) {
            const ulonglong2* brow = (const ulonglong2*)&Bb[k * 128 + tx * 8];
            ulonglong2 b01 = brow[0];
            ulonglong2 b23 = brow[1];
            float a[8];
            *(float4*)&a[0] = *(const float4*)&Ab[k * 128 + ty * 8];
            *(float4*)&a[4] = *(const float4*)&Ab[k * 128 + ty * 8 + 4];
            #pragma unroll
            for (int i = 0; i < 8; i++) {
                unsigned long long ap = dup2(a[i]);
                acc[i][0] = fma2(ap, b01.x, acc[i][0]);
                acc[i][1] = fma2(ap, b01.y, acc[i][1]);
                acc[i][2] = fma2(ap, b23.x, acc[i][2]);
                acc[i][3] = fma2(ap, b23.y, acc[i][3]);
            }
        }
    }

    float* gout = g_Gbuf + GUARD + (size_t)b * L * L;
    #pragma unroll
    for (int i = 0; i < 8; i++) {
        size_t row = (size_t)(lbase + ty * 8 + i) * L + mbase + tx * 8;
        *(ulonglong2*)&gout[row + 0] = make_ulonglong2(acc[i][0], acc[i][1]);
        *(ulonglong2*)&gout[row + 4] = make_ulonglong2(acc[i][2], acc[i][3]);
    }
}

// ---------------- 4. diagonal 3x3 box filter of G + scaling + column argmax ----------------
// Loads are UNPREDICATED (guard margins in g_Gbuf stay zero) so ptxas can
// front-batch all 18 loads per 2-row iteration; masking is a register select.
__global__ void __launch_bounds__(256) k_boxargmax() {
    int b = blockIdx.z;
    int m = blockIdx.x * 256 + threadIdx.x;
    int l0 = blockIdx.y * LCHUNK;
    int my = m / WW, mx = m % WW;

    __shared__ float sInvA[LCHUNK];
    __shared__ unsigned sLmask[LCHUNK];
    int t = threadIdx.x;
    if (t < LCHUNK) {
        int l = l0 + t, ly = l / WW, lx = l % WW;
        unsigned msk = 0;
        int o = 0;
        #pragma unroll
        for (int dy = -1; dy <= 1; dy++)
            #pragma unroll
            for (int dx = -1; dx <= 1; dx++, o++)
                if ((unsigned)(ly + dy) < HH && (unsigned)(lx + dx) < WW)
                    msk |= 1u << o;
        sLmask[t] = msk;
        sInvA[t] = g_invA[b * L + l];
    }
    __syncthreads();

    unsigned mmask = 0;
    {
        int o = 0;
        #pragma unroll
        for (int dy = -1; dy <= 1; dy++)
            #pragma unroll
            for (int dx = -1; dx <= 1; dx++, o++)
                if ((unsigned)(my + dy) < HH && (unsigned)(mx + dx) < WW)
                    mmask |= 1u << o;
    }

    const float invBm = g_invB[b * L + m];
    const float* gbase = g_Gbuf + GUARD + (size_t)b * L * L + (size_t)l0 * L + m;
    const int doff[9] = {-49 * LP1, -48 * LP1, -47 * LP1, -LP1, 0,
                         LP1, 47 * LP1, 48 * LP1, 49 * LP1};

    float best = -1e30f;
    int barg = l0;
    for (int i = 0; i < LCHUNK; i += 2) {
        const float* p0 = gbase + (size_t)i * L;
        const float* p1 = p0 + L;
        float v0[9], v1[9];
        #pragma unroll
        for (int o = 0; o < 9; o++) {
            v0[o] = __ldg(p0 + doff[o]);   // unconditional: guards are zero
            v1[o] = __ldg(p1 + doff[o]);
        }
        unsigned m0 = sLmask[i] & mmask;
        unsigned m1 = sLmask[i + 1] & mmask;
        float s0 = 0.f, s1 = 0.f;
        #pragma unroll
        for (int o = 0; o < 9; o++) {
            s0 += ((m0 >> o) & 1) ? v0[o] : 0.f;
            s1 += ((m1 >> o) & 1) ? v1[o] : 0.f;
        }
        float w0 = s0 * sInvA[i] * invBm;
        float w1 = s1 * sInvA[i + 1] * invBm;
        if (w0 > best) { best = w0; barg = l0 + i; }
        if (w1 > best) { best = w1; barg = l0 + i + 1; }
    }

    unsigned long long pk = ((unsigned long long)fkey(best) << 32) |
                            (unsigned long long)(0xFFFFFFFFu - (unsigned)barg);
    atomicMax(&g_best[b * L + m], pk);
}

// ---------------- 5. decode best -> S output + arg indices ----------------
__global__ void k_decode(float* __restrict__ outS) {
    int i = blockIdx.x * blockDim.x + threadIdx.x;
    if (i >= BATCH * L) return;
    unsigned long long p = g_best[i];
    outS[i] = fkeyinv((unsigned)(p >> 32));
    g_arg[i] = (int)(0xFFFFFFFFu - (unsigned)(p & 0xFFFFFFFFu));
}

// ---------------- 6. gather + fold, channel-blocked, fixed-9 masked loads ----------------
__global__ void k_gather(const float* __restrict__ ref, float* __restrict__ out,
                         int C, int s, int Hs) {
    int b = blockIdx.z;
    int cbase = blockIdx.y * 8;
    int p = blockIdx.x * blockDim.x + threadIdx.x;
    int y = p / Hs, x = p % Hs;
    int qy = y / s, ry = y % s, qx = x / s, rxr = x % s;
    const int* argb = g_arg + b * L;

    // fixed 9 slots: (offset, weight) — invalid slots read offset 0 with weight 0
    int off[9];
    float w[9];
    {
        int o = 0;
        #pragma unroll
        for (int dy = 0; dy < 3; dy++) {
            int oh = qy + 1 - dy;
            int ki = ry + s * dy;
            #pragma unroll
            for (int dx = 0; dx < 3; dx++, o++) {
                int ow = qx + 1 - dx;
                int kj = rxr + s * dx;
                bool v = (unsigned)oh < HH && (unsigned)ow < WW;
                int j = v ? __ldg(argb + oh * WW + ow) : 0;
                int sy = s * (j / WW) + ki - s;
                int sx = s * (j % WW) + kj - s;
                v = v && (unsigned)sy < (unsigned)Hs && (unsigned)sx < (unsigned)Hs;
                off[o] = v ? (sy * Hs + sx) : 0;
                w[o] = v ? 1.f : 0.f;
            }
        }
    }

    size_t plane = (size_t)Hs * Hs;
    const float* refc = ref + ((size_t)b * C + cbase) * plane;
    float* outc = out + ((size_t)b * C + cbase) * plane + p;
    #pragma unroll
    for (int cc = 0; cc < 8; cc++) {
        const float* rp = refc + (size_t)cc * plane;
        float sum = 0.f;
        #pragma unroll
        for (int o = 0; o < 9; o++)
            sum = fmaf(w[o], __ldg(rp + off[o]), sum);
        outc[(size_t)cc * plane] = sum * (1.f / 9.f);
    }
}

// ---------------- launch ----------------
extern "C" void kernel_launch(void* const* d_in, const int* in_sizes, int n_in,
                              void* d_out, int out_size) {
    const float* lrsr = (const float*)d_in[0];
    const float* refsr = (const float*)d_in[1];
    const float* ref1 = (const float*)d_in[2];
    const float* ref2 = (const float*)d_in[3];
    const float* ref3 = (const float*)d_in[4];
    float* out = (float*)d_out;

    float* outS = out;                            // (4,1,48,48)
    float* outT3 = outS + BATCH * L;              // (4,256,48,48)
    float* outT2 = outT3 + BATCH * C3 * HH * WW;  // (4,128,96,96)
    float* outT1 = outT2 + BATCH * 128 * 96 * 96; // (4,64,192,192)

    // idempotent, capture-safe (not a stream op); called unconditionally
    cudaFuncSetAttribute(k_gemmG, cudaFuncAttributeMaxDynamicSharedMemorySize,
                         GEMM_SMEM);

    k_init<<<(BATCH * L + 255) / 256, 256>>>();
    k_sqsum<<<dim3(9, 8, BATCH), 256>>>(lrsr, refsr);
    k_norms<<<(BATCH * L + 255) / 256, 256>>>();
    k_gemmG<<<dim3(18, 18, BATCH), 256, GEMM_SMEM>>>(refsr, lrsr);
    k_boxargmax<<<dim3(9, 36, BATCH), 256>>>();
    k_decode<<<(BATCH * L + 255) / 256, 256>>>(outS);
    k_gather<<<dim3(2304 / 256, 256 / 8, BATCH), 256>>>(ref3, outT3, C3, 1, 48);
    k_gather<<<dim3(9216 / 256, 128 / 8, BATCH), 256>>>(ref2, outT2, 128, 2, 96);
    k_gather<<<dim3(36864 / 256, 64 / 8, BATCH), 256>>>(ref1, outT1, 64, 4, 192);
}